// round 3
// baseline (speedup 1.0000x reference)
#include <cuda_runtime.h>

// ============================================================================
// StyleGAN2 ModulatedConv2D, fused as one shared-weight implicit GEMM.
//   s[n,ci]   = dlatent[n] @ mod_weight * RC_S + mod_bias + 1
//   wsq[ci,co]= sum_kk weight[kk,ci,co]^2
//   d[n,co]   = rsqrt(RC_W^2 * sum_ci s^2 * wsq + 1e-8)
//   out[n,co] = d[n,co]*RC_W * conv2d( s[n,ci]*x[n,ci], weight )   (SAME pad)
// Conv = GEMM: M = pixels (per image), N = cout, K = 9*512 = 4608.
// Weight layout [kk,ci,co] is already the row-major B[K, 512] matrix.
// ============================================================================

#define CIN     512
#define COUT    512
#define LATENTD 512
#define HH      64
#define WWID    64
#define NBATCH  8
#define HW      (HH * WWID)
#define KTOT    (9 * CIN)          // 4608
#define NKC     (KTOT / 16)        // 288 k-chunks

#define RC_W 0.014731391274719738f   // 1/sqrt(9*512)
#define RC_S 0.04419417382415922f    // 1/sqrt(512)

__device__ float g_style[NBATCH * CIN];
__device__ float g_demod[NBATCH * COUT];
__device__ float g_wsq[CIN * COUT];

// ---------------- packed f32x2 helpers (full-rate fp32 on sm_103a) ----------
__device__ __forceinline__ unsigned long long pack2(float v) {
    unsigned long long r;
    unsigned u = __float_as_uint(v);
    asm("mov.b64 %0, {%1, %1};" : "=l"(r) : "r"(u));
    return r;
}
__device__ __forceinline__ void ffma2(unsigned long long& d,
                                      unsigned long long a,
                                      unsigned long long b) {
    asm("fma.rn.f32x2 %0, %1, %2, %0;" : "+l"(d) : "l"(a), "l"(b));
}
__device__ __forceinline__ float2 unpack2(unsigned long long v) {
    float2 f;
    asm("mov.b64 {%0, %1}, %2;" : "=f"(f.x), "=f"(f.y) : "l"(v));
    return f;
}

// ---------------- prologue kernels ------------------------------------------
__global__ void style_k(const float* __restrict__ dl,
                        const float* __restrict__ mw,
                        const float* __restrict__ mb) {
    const int n  = blockIdx.x;
    const int ci = threadIdx.x;
    __shared__ float dls[LATENTD];
    dls[ci] = dl[n * LATENTD + ci];
    __syncthreads();
    float acc = 0.0f;
#pragma unroll 8
    for (int l = 0; l < LATENTD; l++)
        acc += dls[l] * mw[l * CIN + ci];
    g_style[n * CIN + ci] = acc * RC_S + mb[ci] + 1.0f;
}

__global__ void wsq_k(const float* __restrict__ w) {
    const int idx = blockIdx.x * 256 + threadIdx.x;   // ci*512 + co
    float acc = 0.0f;
#pragma unroll
    for (int kk = 0; kk < 9; kk++) {
        float v = w[kk * (CIN * COUT) + idx];
        acc += v * v;
    }
    g_wsq[idx] = acc;
}

__global__ void demod_k() {
    const int n  = blockIdx.x;
    const int co = threadIdx.x;
    __shared__ float s2[CIN];
    float sv = g_style[n * CIN + co];
    s2[co] = sv * sv;
    __syncthreads();
    float acc = 0.0f;
#pragma unroll 8
    for (int ci = 0; ci < CIN; ci++)
        acc += s2[ci] * g_wsq[ci * COUT + co];
    g_demod[n * COUT + co] = rsqrtf(acc * (RC_W * RC_W) + 1e-8f);
}

// ---------------- main conv: 128x128x16 implicit GEMM, f32x2 microkernel ----
__global__ __launch_bounds__(256) void conv_k(const float* __restrict__ x,
                                              const float* __restrict__ w,
                                              float* __restrict__ out) {
    __shared__ __align__(16) float As[2][16][128];
    __shared__ __align__(16) float Bs[2][16][128];
    __shared__ float s_sm[CIN];

    const int tid = threadIdx.x;
    const int n   = blockIdx.z;
    const int co0 = blockIdx.y * 128;
    const int m0  = blockIdx.x * 128;

    s_sm[tid]       = g_style[n * CIN + tid];
    s_sm[tid + 256] = g_style[n * CIN + tid + 256];
    __syncthreads();

    // A-load indices: each thread owns one pixel (mA), 8 k values {kA+2i}
    const int mA = tid & 127;
    const int kA = tid >> 7;                  // 0 or 1
    const int yA = (m0 + mA) >> 6;
    const int xA = (m0 + mA) & 63;
    const float* xn = x + (size_t)n * CIN * HW;

    // B-load indices
    const int cB = tid & 127;
    const int kB = tid >> 7;
    const float* wB = w + co0 + cB;

    float ra[8], rb[8];

    auto load_tiles = [&](int kc, float* rA, float* rB) {
        const int kg0 = kc << 4;
        const int kk  = kg0 >> 9;             // constant within a 16-chunk
        const int ci0 = kg0 & 511;
        const int kkd = kk / 3;
        const int dy  = kkd - 1;
        const int dx  = kk - kkd * 3 - 1;
        const int yy  = yA + dy;
        const int xx  = xA + dx;
        const bool inb = ((unsigned)yy < 64u) && ((unsigned)xx < 64u);
        const int off = (yy << 6) + xx;
#pragma unroll
        for (int i = 0; i < 8; i++) {
            const int ci = ci0 + kA + 2 * i;
            rA[i] = inb ? xn[ci * HW + off] * s_sm[ci] : 0.0f;
        }
        const float* wp = wB + (size_t)(kg0 + kB) * COUT;
#pragma unroll
        for (int i = 0; i < 8; i++)
            rB[i] = wp[2 * i * COUT];
    };

    auto store_tiles = [&](int buf, const float* rA, const float* rB) {
#pragma unroll
        for (int i = 0; i < 8; i++) {
            As[buf][kA + 2 * i][mA] = rA[i];
            Bs[buf][kB + 2 * i][cB] = rB[i];
        }
    };

    // compute mapping: tm fast (m contiguous per thread -> coalesced stores)
    const int tm = tid & 15;
    const int tn = tid >> 4;

    unsigned long long acc[8][4];
#pragma unroll
    for (int i = 0; i < 8; i++)
#pragma unroll
        for (int j = 0; j < 4; j++) acc[i][j] = 0ull;

    load_tiles(0, ra, rb);
    store_tiles(0, ra, rb);
    __syncthreads();

    for (int kc = 0; kc < NKC; kc++) {
        const int buf = kc & 1;
        if (kc + 1 < NKC) load_tiles(kc + 1, ra, rb);

#pragma unroll
        for (int k = 0; k < 16; k++) {
            const float4 a0 = *(const float4*)&As[buf][k][tm * 8];
            const float4 a1 = *(const float4*)&As[buf][k][tm * 8 + 4];
            const ulonglong2 bb0 = *(const ulonglong2*)&Bs[buf][k][tn * 8];
            const ulonglong2 bb1 = *(const ulonglong2*)&Bs[buf][k][tn * 8 + 4];
            const unsigned long long b2[4] = {bb0.x, bb0.y, bb1.x, bb1.y};
            const float af[8] = {a0.x, a0.y, a0.z, a0.w, a1.x, a1.y, a1.z, a1.w};
#pragma unroll
            for (int ii = 0; ii < 8; ii++) {
                const unsigned long long a2 = pack2(af[ii]);
#pragma unroll
                for (int j = 0; j < 4; j++) ffma2(acc[ii][j], a2, b2[j]);
            }
        }

        if (kc + 1 < NKC) store_tiles(buf ^ 1, ra, rb);
        __syncthreads();
    }

    // epilogue: scale by RC_W * demod, coalesced float4 stores
    const int pbase = m0 + tm * 8;
#pragma unroll
    for (int j = 0; j < 4; j++) {
        const int co = co0 + tn * 8 + 2 * j;
        const float d0 = g_demod[n * COUT + co]     * RC_W;
        const float d1 = g_demod[n * COUT + co + 1] * RC_W;
        float2 u[8];
#pragma unroll
        for (int ii = 0; ii < 8; ii++) u[ii] = unpack2(acc[ii][j]);
        float* o0 = out + ((size_t)(n * COUT + co)) * HW + pbase;
        float* o1 = o0 + HW;
        *(float4*)(o0)     = make_float4(u[0].x * d0, u[1].x * d0, u[2].x * d0, u[3].x * d0);
        *(float4*)(o0 + 4) = make_float4(u[4].x * d0, u[5].x * d0, u[6].x * d0, u[7].x * d0);
        *(float4*)(o1)     = make_float4(u[0].y * d1, u[1].y * d1, u[2].y * d1, u[3].y * d1);
        *(float4*)(o1 + 4) = make_float4(u[4].y * d1, u[5].y * d1, u[6].y * d1, u[7].y * d1);
    }
}

// ---------------- launch -----------------------------------------------------
extern "C" void kernel_launch(void* const* d_in, const int* in_sizes, int n_in,
                              void* d_out, int out_size) {
    const float* x  = (const float*)d_in[0];   // [8,512,64,64]
    const float* dl = (const float*)d_in[1];   // [8,512]
    const float* w  = (const float*)d_in[2];   // [3,3,512,512]
    const float* mw = (const float*)d_in[3];   // [512,512]
    const float* mb = (const float*)d_in[4];   // [512]
    float* out = (float*)d_out;                // [8,512,64,64]

    style_k<<<NBATCH, 512>>>(dl, mw, mb);
    wsq_k<<<(CIN * COUT) / 256, 256>>>(w);
    demod_k<<<NBATCH, 512>>>();
    conv_k<<<dim3(HW / 128, COUT / 128, NBATCH), 256>>>(x, w, out);
}

// round 7
// speedup vs baseline: 4.7477x; 4.7477x over previous
#include <cuda_runtime.h>
#include <cuda_fp16.h>
#include <cstdint>

// ============================================================================
// StyleGAN2 ModulatedConv2D via mma.sync (HMMA fp16, fp32 accum).
// Base-target features only: ldmatrix / mma.sync / cp.async.
// Implicit GEMM per image: M=4096 pixels, N=512 couts, K=9*512=4608.
// smem: padded-pitch 80B rows (64B payload) -> conflict-free ldmatrix,
// no swizzle, all offsets bounded by construction. 2-stage cp.async pipeline.
// ============================================================================

#define CIN     512
#define COUT    512
#define LATENTD 512
#define NBATCH  8
#define HW      4096
#define KTOT    4608
#define NCH     144               // K chunks of 32 (9 kk * 16 ci-chunks)
#define PITCH   80                // 64B payload + 16B pad
#define A_BYTES (128 * PITCH)     // 10240
#define STG_B   (2 * A_BYTES)     // A + B = 20480
#define SMEM_SZ (2 * STG_B)       // 40960 (static, < 48KB)

#define RC_W 0.014731391274719738f   // 1/sqrt(9*512)
#define RC_S 0.04419417382415922f    // 1/sqrt(512)

__device__ float g_style[NBATCH * CIN];
__device__ float g_demod[NBATCH * COUT];
__device__ float g_wsq[CIN * COUT];
__device__ __align__(16) __half g_xh[(size_t)NBATCH * HW * CIN];  // [n][p][ci]
__device__ __align__(16) __half g_wh[(size_t)COUT * KTOT];        // [co][k]

// ---------------- PTX helpers ----------------------------------------------
__device__ __forceinline__ uint32_t smem_u32(const void* p) {
    uint32_t a;
    asm("{ .reg .u64 t; cvta.to.shared.u64 t, %1; cvt.u32.u64 %0, t; }"
        : "=r"(a) : "l"(p));
    return a;
}
__device__ __forceinline__ void cp16(uint32_t s, const void* g, uint32_t sz) {
    asm volatile("cp.async.cg.shared.global [%0], [%1], 16, %2;"
                 :: "r"(s), "l"(g), "r"(sz) : "memory");
}
#define CP_COMMIT() asm volatile("cp.async.commit_group;" ::: "memory")
#define CP_WAIT1()  asm volatile("cp.async.wait_group 1;" ::: "memory")
#define CP_WAIT0()  asm volatile("cp.async.wait_group 0;" ::: "memory")

#define LDSM4(r, addr) \
    asm volatile("ldmatrix.sync.aligned.m8n8.x4.shared.b16 {%0,%1,%2,%3}, [%4];" \
                 : "=r"((r)[0]), "=r"((r)[1]), "=r"((r)[2]), "=r"((r)[3]) \
                 : "r"(addr))

#define MMA16816(d, a, b0, b1) \
    asm volatile("mma.sync.aligned.m16n8k16.row.col.f32.f16.f16.f32 " \
                 "{%0,%1,%2,%3},{%4,%5,%6,%7},{%8,%9},{%0,%1,%2,%3};" \
                 : "+f"((d)[0]), "+f"((d)[1]), "+f"((d)[2]), "+f"((d)[3]) \
                 : "r"((a)[0]), "r"((a)[1]), "r"((a)[2]), "r"((a)[3]), \
                   "r"(b0), "r"(b1))

// ---------------- prologue kernels (validated in R3) ------------------------
__global__ void style_k(const float* __restrict__ dl,
                        const float* __restrict__ mw,
                        const float* __restrict__ mb) {
    const int n = blockIdx.x, ci = threadIdx.x;
    __shared__ float dls[LATENTD];
    dls[ci] = dl[n * LATENTD + ci];
    __syncthreads();
    float acc = 0.0f;
#pragma unroll 8
    for (int l = 0; l < LATENTD; l++) acc += dls[l] * mw[l * CIN + ci];
    g_style[n * CIN + ci] = acc * RC_S + mb[ci] + 1.0f;
}

__global__ void wsq_k(const float* __restrict__ w) {
    const int idx = blockIdx.x * 256 + threadIdx.x;
    float acc = 0.0f;
#pragma unroll
    for (int kk = 0; kk < 9; kk++) {
        float v = w[kk * (CIN * COUT) + idx];
        acc += v * v;
    }
    g_wsq[idx] = acc;
}

__global__ void demod_k() {
    const int n = blockIdx.x, co = threadIdx.x;
    __shared__ float s2[CIN];
    float sv = g_style[n * CIN + co];
    s2[co] = sv * sv;
    __syncthreads();
    float acc = 0.0f;
#pragma unroll 8
    for (int ci = 0; ci < CIN; ci++) acc += s2[ci] * g_wsq[ci * COUT + co];
    g_demod[n * COUT + co] = rsqrtf(acc * (RC_W * RC_W) + 1e-8f);
}

// weight [k][co] fp32 -> g_wh [co][k] fp16 (transpose)
__global__ void wcvt_k(const float* __restrict__ w) {
    __shared__ float t[32][33];
    const int tx = threadIdx.x, ty = threadIdx.y;
    const int co0 = blockIdx.x * 32, k0 = blockIdx.y * 32;
#pragma unroll
    for (int i = 0; i < 4; i++)
        t[ty + i * 8][tx] = w[(size_t)(k0 + ty + i * 8) * COUT + co0 + tx];
    __syncthreads();
#pragma unroll
    for (int i = 0; i < 4; i++)
        g_wh[(size_t)(co0 + ty + i * 8) * KTOT + k0 + tx] =
            __float2half(t[tx][ty + i * 8]);
}

// x [n][ci][p] * s[n][ci] -> g_xh [n][p][ci] fp16 (transpose + modulate)
__global__ void xcvt_k(const float* __restrict__ x) {
    __shared__ float t[32][33];
    const int tx = threadIdx.x, ty = threadIdx.y;
    const int p0 = blockIdx.x * 32, ci0 = blockIdx.y * 32, n = blockIdx.z;
#pragma unroll
    for (int i = 0; i < 4; i++) {
        const int ci = ci0 + ty + i * 8;
        t[ty + i * 8][tx] =
            x[((size_t)n * CIN + ci) * HW + p0 + tx] * g_style[n * CIN + ci];
    }
    __syncthreads();
#pragma unroll
    for (int i = 0; i < 4; i++)
        g_xh[((size_t)n * HW + p0 + ty + i * 8) * CIN + ci0 + tx] =
            __float2half(t[tx][ty + i * 8]);
}

// ---------------- main conv: 128x128 CTA, warp 64x32, K-chunks of 32 --------
__global__ void __launch_bounds__(256, 2) conv_k(float* __restrict__ out) {
    __shared__ __align__(128) char dsm[SMEM_SZ];

    const int tid = threadIdx.x;
    const int wid = tid >> 5, lane = tid & 31;
    const int n = blockIdx.z;
    const int co0 = blockIdx.y * 128;
    const int m0 = blockIdx.x * 128;
    const int wm = (wid & 1) * 64;       // warp M offset
    const int wn = (wid >> 1) * 32;      // warp N offset

    const uint32_t sbase = smem_u32(dsm);

    // ---- cp.async geometry: thread t owns row (t>>1), half (t&1) ----
    const int arow = tid >> 1, ahalf = tid & 1;
    const int ya = (m0 + arow) >> 6, xa = (m0 + arow) & 63;
    const uint32_t rc_st = (uint32_t)(arow * PITCH + ahalf * 32);
    const __half* gb_base = g_wh + (size_t)(co0 + arow) * KTOT + ahalf * 16;

    auto issue = [&](int j) {
        const int st = j & 1;
        const int kk = j >> 4;
        const int ci0 = (j & 15) << 5;
        const int dy = kk / 3 - 1, dx = kk - (kk / 3) * 3 - 1;
        const int yy = ya + dy, xx = xa + dx;
        const bool inb = ((unsigned)yy < 64u) && ((unsigned)xx < 64u);
        const int pp = inb ? (yy * 64 + xx) : 0;
        const uint32_t sz = inb ? 16u : 0u;
        const __half* ga = g_xh + ((size_t)n * HW + pp) * CIN + ci0 + ahalf * 16;
        const uint32_t ab = sbase + st * STG_B + rc_st;
        cp16(ab, ga, sz);
        cp16(ab + 16, ga + 8, sz);
        const __half* gb = gb_base + kk * 512 + ci0;
        const uint32_t bb = ab + A_BYTES;
        cp16(bb, gb, 16u);
        cp16(bb + 16, gb + 8, 16u);
    };

    // ---- ldmatrix per-lane offsets (k16 step adds +32) ----
    uint32_t a_off[4], b_off[2];
#pragma unroll
    for (int mt = 0; mt < 4; mt++)
        a_off[mt] = (uint32_t)((wm + mt * 16 + (lane & 15)) * PITCH +
                               (lane >> 4) * 16);
#pragma unroll
    for (int bt = 0; bt < 2; bt++)
        b_off[bt] = (uint32_t)(
            (wn + bt * 16 + (lane & 7) + ((lane >> 4) & 1) * 8) * PITCH +
            ((lane >> 3) & 1) * 16) + A_BYTES;

    float acc[4][4][4];
#pragma unroll
    for (int mt = 0; mt < 4; mt++)
#pragma unroll
        for (int nt = 0; nt < 4; nt++)
#pragma unroll
            for (int r = 0; r < 4; r++) acc[mt][nt][r] = 0.0f;

    issue(0); CP_COMMIT();
    issue(1); CP_COMMIT();

    for (int i = 0; i < NCH; i++) {
        CP_WAIT1();
        __syncthreads();                       // stage-i data visible to all
        const uint32_t stB = sbase + (i & 1) * STG_B;
#pragma unroll
        for (int ks = 0; ks < 2; ks++) {
            uint32_t af[4][4], bf[2][4];
#pragma unroll
            for (int mt = 0; mt < 4; mt++)
                LDSM4(af[mt], stB + a_off[mt] + ks * 32);
#pragma unroll
            for (int bt = 0; bt < 2; bt++)
                LDSM4(bf[bt], stB + b_off[bt] + ks * 32);
#pragma unroll
            for (int mt = 0; mt < 4; mt++) {
                MMA16816(acc[mt][0], af[mt], bf[0][0], bf[0][1]);
                MMA16816(acc[mt][1], af[mt], bf[0][2], bf[0][3]);
                MMA16816(acc[mt][2], af[mt], bf[1][0], bf[1][1]);
                MMA16816(acc[mt][3], af[mt], bf[1][2], bf[1][3]);
            }
        }
        __syncthreads();                       // all reads done before overwrite
        if (i + 2 < NCH) issue(i + 2);
        CP_COMMIT();
    }
    CP_WAIT0();                                // nothing outstanding at exit

    // ---- epilogue: scale by demod*RC_W ----
    const float* dm = g_demod + n * COUT;
#pragma unroll
    for (int nt = 0; nt < 4; nt++) {
        const int cb = co0 + wn + nt * 8 + (lane & 3) * 2;
        const float d0 = dm[cb] * RC_W;
        const float d1 = dm[cb + 1] * RC_W;
#pragma unroll
        for (int mt = 0; mt < 4; mt++) {
            const int mrow = m0 + wm + mt * 16 + (lane >> 2);
            float* o = out + ((size_t)(n * COUT + cb)) * HW + mrow;
            o[0]      = acc[mt][nt][0] * d0;
            o[HW]     = acc[mt][nt][1] * d1;
            o[8]      = acc[mt][nt][2] * d0;
            o[HW + 8] = acc[mt][nt][3] * d1;
        }
    }
}

// ---------------- launch -----------------------------------------------------
extern "C" void kernel_launch(void* const* d_in, const int* in_sizes, int n_in,
                              void* d_out, int out_size) {
    const float* x  = (const float*)d_in[0];   // [8,512,64,64]
    const float* dl = (const float*)d_in[1];   // [8,512]
    const float* w  = (const float*)d_in[2];   // [3,3,512,512]
    const float* mw = (const float*)d_in[3];   // [512,512]
    const float* mb = (const float*)d_in[4];   // [512]
    float* out = (float*)d_out;                // [8,512,64,64]

    style_k<<<NBATCH, 512>>>(dl, mw, mb);
    wsq_k<<<(CIN * COUT) / 256, 256>>>(w);
    demod_k<<<NBATCH, 512>>>();
    wcvt_k<<<dim3(COUT / 32, KTOT / 32), dim3(32, 8)>>>(w);
    xcvt_k<<<dim3(HW / 32, CIN / 32, NBATCH), dim3(32, 8)>>>(x);
    conv_k<<<dim3(HW / 128, COUT / 128, NBATCH), 256>>>(out);
}

// round 8
// speedup vs baseline: 5.4042x; 1.1383x over previous
#include <cuda_runtime.h>
#include <cuda_fp16.h>
#include <cstdint>

// ============================================================================
// StyleGAN2 ModulatedConv2D via mma.sync (HMMA fp16, fp32 accum).
// Base-target features only: ldmatrix / mma.sync / cp.async.
// Implicit GEMM per image: M=4096 pixels, N=512 couts, K=9*512=4608.
// smem: padded-pitch 80B rows (64B payload) -> conflict-free ldmatrix.
// R8: 3-stage cp.async pipeline (dynamic smem), ONE __syncthreads per iter,
//     prefetch distance 2 chunks.
// ============================================================================

#define CIN     512
#define COUT    512
#define LATENTD 512
#define NBATCH  8
#define HW      4096
#define KTOT    4608
#define NCH     144               // K chunks of 32 (9 kk * 16 ci-chunks)
#define NSTG    3
#define PITCH   80                // 64B payload + 16B pad
#define A_BYTES (128 * PITCH)     // 10240
#define STG_B   (2 * A_BYTES)     // A + B = 20480
#define SMEM_SZ (NSTG * STG_B)    // 61440 dynamic

#define RC_W 0.014731391274719738f   // 1/sqrt(9*512)
#define RC_S 0.04419417382415922f    // 1/sqrt(512)

__device__ float g_style[NBATCH * CIN];
__device__ float g_demod[NBATCH * COUT];
__device__ float g_wsq[CIN * COUT];
__device__ __align__(16) __half g_xh[(size_t)NBATCH * HW * CIN];  // [n][p][ci]
__device__ __align__(16) __half g_wh[(size_t)COUT * KTOT];        // [co][k]

// ---------------- PTX helpers ----------------------------------------------
__device__ __forceinline__ uint32_t smem_u32(const void* p) {
    uint32_t a;
    asm("{ .reg .u64 t; cvta.to.shared.u64 t, %1; cvt.u32.u64 %0, t; }"
        : "=r"(a) : "l"(p));
    return a;
}
__device__ __forceinline__ void cp16(uint32_t s, const void* g, uint32_t sz) {
    asm volatile("cp.async.cg.shared.global [%0], [%1], 16, %2;"
                 :: "r"(s), "l"(g), "r"(sz) : "memory");
}
#define CP_COMMIT() asm volatile("cp.async.commit_group;" ::: "memory")
#define CP_WAIT1()  asm volatile("cp.async.wait_group 1;" ::: "memory")
#define CP_WAIT0()  asm volatile("cp.async.wait_group 0;" ::: "memory")

#define LDSM4(r, addr) \
    asm volatile("ldmatrix.sync.aligned.m8n8.x4.shared.b16 {%0,%1,%2,%3}, [%4];" \
                 : "=r"((r)[0]), "=r"((r)[1]), "=r"((r)[2]), "=r"((r)[3]) \
                 : "r"(addr))

#define MMA16816(d, a, b0, b1) \
    asm volatile("mma.sync.aligned.m16n8k16.row.col.f32.f16.f16.f32 " \
                 "{%0,%1,%2,%3},{%4,%5,%6,%7},{%8,%9},{%0,%1,%2,%3};" \
                 : "+f"((d)[0]), "+f"((d)[1]), "+f"((d)[2]), "+f"((d)[3]) \
                 : "r"((a)[0]), "r"((a)[1]), "r"((a)[2]), "r"((a)[3]), \
                   "r"(b0), "r"(b1))

// ---------------- prologue kernels (validated) ------------------------------
__global__ void style_k(const float* __restrict__ dl,
                        const float* __restrict__ mw,
                        const float* __restrict__ mb) {
    const int n = blockIdx.x, ci = threadIdx.x;
    __shared__ float dls[LATENTD];
    dls[ci] = dl[n * LATENTD + ci];
    __syncthreads();
    float acc = 0.0f;
#pragma unroll 8
    for (int l = 0; l < LATENTD; l++) acc += dls[l] * mw[l * CIN + ci];
    g_style[n * CIN + ci] = acc * RC_S + mb[ci] + 1.0f;
}

__global__ void wsq_k(const float* __restrict__ w) {
    const int idx = blockIdx.x * 256 + threadIdx.x;
    float acc = 0.0f;
#pragma unroll
    for (int kk = 0; kk < 9; kk++) {
        float v = w[kk * (CIN * COUT) + idx];
        acc += v * v;
    }
    g_wsq[idx] = acc;
}

__global__ void demod_k() {
    const int n = blockIdx.x, co = threadIdx.x;
    __shared__ float s2[CIN];
    float sv = g_style[n * CIN + co];
    s2[co] = sv * sv;
    __syncthreads();
    float acc = 0.0f;
#pragma unroll 8
    for (int ci = 0; ci < CIN; ci++) acc += s2[ci] * g_wsq[ci * COUT + co];
    g_demod[n * COUT + co] = rsqrtf(acc * (RC_W * RC_W) + 1e-8f);
}

// weight [k][co] fp32 -> g_wh [co][k] fp16 (transpose)
__global__ void wcvt_k(const float* __restrict__ w) {
    __shared__ float t[32][33];
    const int tx = threadIdx.x, ty = threadIdx.y;
    const int co0 = blockIdx.x * 32, k0 = blockIdx.y * 32;
#pragma unroll
    for (int i = 0; i < 4; i++)
        t[ty + i * 8][tx] = w[(size_t)(k0 + ty + i * 8) * COUT + co0 + tx];
    __syncthreads();
#pragma unroll
    for (int i = 0; i < 4; i++)
        g_wh[(size_t)(co0 + ty + i * 8) * KTOT + k0 + tx] =
            __float2half(t[tx][ty + i * 8]);
}

// x [n][ci][p] * s[n][ci] -> g_xh [n][p][ci] fp16 (transpose + modulate)
__global__ void xcvt_k(const float* __restrict__ x) {
    __shared__ float t[32][33];
    const int tx = threadIdx.x, ty = threadIdx.y;
    const int p0 = blockIdx.x * 32, ci0 = blockIdx.y * 32, n = blockIdx.z;
#pragma unroll
    for (int i = 0; i < 4; i++) {
        const int ci = ci0 + ty + i * 8;
        t[ty + i * 8][tx] =
            x[((size_t)n * CIN + ci) * HW + p0 + tx] * g_style[n * CIN + ci];
    }
    __syncthreads();
#pragma unroll
    for (int i = 0; i < 4; i++)
        g_xh[((size_t)n * HW + p0 + ty + i * 8) * CIN + ci0 + tx] =
            __float2half(t[tx][ty + i * 8]);
}

// ---------------- main conv: 128x128 CTA, warp 64x32, K-chunks of 32 --------
__global__ void __launch_bounds__(256, 2) conv_k(float* __restrict__ out) {
    extern __shared__ __align__(128) char dsm[];

    const int tid = threadIdx.x;
    const int wid = tid >> 5, lane = tid & 31;
    const int n = blockIdx.z;
    const int co0 = blockIdx.y * 128;
    const int m0 = blockIdx.x * 128;
    const int wm = (wid & 1) * 64;       // warp M offset
    const int wn = (wid >> 1) * 32;      // warp N offset

    const uint32_t sbase = smem_u32(dsm);

    // ---- cp.async geometry: thread t owns row (t>>1), half (t&1) ----
    const int arow = tid >> 1, ahalf = tid & 1;
    const int ya = (m0 + arow) >> 6, xa = (m0 + arow) & 63;
    const uint32_t rc_st = (uint32_t)(arow * PITCH + ahalf * 32);
    const __half* gb_base = g_wh + (size_t)(co0 + arow) * KTOT + ahalf * 16;

    auto issue = [&](int j, int st) {
        const int kk = j >> 4;
        const int ci0 = (j & 15) << 5;
        const int dy = kk / 3 - 1, dx = kk - (kk / 3) * 3 - 1;
        const int yy = ya + dy, xx = xa + dx;
        const bool inb = ((unsigned)yy < 64u) && ((unsigned)xx < 64u);
        const int pp = inb ? (yy * 64 + xx) : 0;
        const uint32_t sz = inb ? 16u : 0u;
        const __half* ga = g_xh + ((size_t)n * HW + pp) * CIN + ci0 + ahalf * 16;
        const uint32_t ab = sbase + st * STG_B + rc_st;
        cp16(ab, ga, sz);
        cp16(ab + 16, ga + 8, sz);
        const __half* gb = gb_base + kk * 512 + ci0;
        const uint32_t bb = ab + A_BYTES;
        cp16(bb, gb, 16u);
        cp16(bb + 16, gb + 8, 16u);
    };

    // ---- ldmatrix per-lane offsets (k16 step adds +32) ----
    uint32_t a_off[4], b_off[2];
#pragma unroll
    for (int mt = 0; mt < 4; mt++)
        a_off[mt] = (uint32_t)((wm + mt * 16 + (lane & 15)) * PITCH +
                               (lane >> 4) * 16);
#pragma unroll
    for (int bt = 0; bt < 2; bt++)
        b_off[bt] = (uint32_t)(
            (wn + bt * 16 + (lane & 7) + ((lane >> 4) & 1) * 8) * PITCH +
            ((lane >> 3) & 1) * 16) + A_BYTES;

    float acc[4][4][4];
#pragma unroll
    for (int mt = 0; mt < 4; mt++)
#pragma unroll
        for (int nt = 0; nt < 4; nt++)
#pragma unroll
            for (int r = 0; r < 4; r++) acc[mt][nt][r] = 0.0f;

    issue(0, 0); CP_COMMIT();
    issue(1, 1); CP_COMMIT();

    int st = 0;                   // stage of chunk i
    int stw = 2;                  // stage for chunk i+2
    for (int i = 0; i < NCH; i++) {
        CP_WAIT1();               // chunk i's group complete (2 outstanding max)
        __syncthreads();          // stage-i visible; all warps done reading i-1
        const uint32_t stB = sbase + st * STG_B;
#pragma unroll
        for (int ks = 0; ks < 2; ks++) {
            uint32_t af[4][4], bf[2][4];
#pragma unroll
            for (int mt = 0; mt < 4; mt++)
                LDSM4(af[mt], stB + a_off[mt] + ks * 32);
#pragma unroll
            for (int bt = 0; bt < 2; bt++)
                LDSM4(bf[bt], stB + b_off[bt] + ks * 32);
#pragma unroll
            for (int mt = 0; mt < 4; mt++) {
                MMA16816(acc[mt][0], af[mt], bf[0][0], bf[0][1]);
                MMA16816(acc[mt][1], af[mt], bf[0][2], bf[0][3]);
                MMA16816(acc[mt][2], af[mt], bf[1][0], bf[1][1]);
                MMA16816(acc[mt][3], af[mt], bf[1][2], bf[1][3]);
            }
        }
        if (i + 2 < NCH) issue(i + 2, stw);   // slot (i-1)%3: reads proven done
        CP_COMMIT();
        st = (st == 2) ? 0 : st + 1;
        stw = (stw == 2) ? 0 : stw + 1;
    }
    CP_WAIT0();

    // ---- epilogue: scale by demod*RC_W ----
    const float* dm = g_demod + n * COUT;
#pragma unroll
    for (int nt = 0; nt < 4; nt++) {
        const int cb = co0 + wn + nt * 8 + (lane & 3) * 2;
        const float d0 = dm[cb] * RC_W;
        const float d1 = dm[cb + 1] * RC_W;
#pragma unroll
        for (int mt = 0; mt < 4; mt++) {
            const int mrow = m0 + wm + mt * 16 + (lane >> 2);
            float* o = out + ((size_t)(n * COUT + cb)) * HW + mrow;
            o[0]      = acc[mt][nt][0] * d0;
            o[HW]     = acc[mt][nt][1] * d1;
            o[8]      = acc[mt][nt][2] * d0;
            o[HW + 8] = acc[mt][nt][3] * d1;
        }
    }
}

// ---------------- launch -----------------------------------------------------
extern "C" void kernel_launch(void* const* d_in, const int* in_sizes, int n_in,
                              void* d_out, int out_size) {
    const float* x  = (const float*)d_in[0];   // [8,512,64,64]
    const float* dl = (const float*)d_in[1];   // [8,512]
    const float* w  = (const float*)d_in[2];   // [3,3,512,512]
    const float* mw = (const float*)d_in[3];   // [512,512]
    const float* mb = (const float*)d_in[4];   // [512]
    float* out = (float*)d_out;                // [8,512,64,64]

    // host-side attribute set: deterministic, capture-legal, no allocation
    cudaFuncSetAttribute(conv_k, cudaFuncAttributeMaxDynamicSharedMemorySize,
                         SMEM_SZ);

    style_k<<<NBATCH, 512>>>(dl, mw, mb);
    wsq_k<<<(CIN * COUT) / 256, 256>>>(w);
    demod_k<<<NBATCH, 512>>>();
    wcvt_k<<<dim3(COUT / 32, KTOT / 32), dim3(32, 8)>>>(w);
    xcvt_k<<<dim3(HW / 32, CIN / 32, NBATCH), dim3(32, 8)>>>(x);
    conv_k<<<dim3(HW / 128, COUT / 128, NBATCH), 256, SMEM_SZ>>>(out);
}

// round 9
// speedup vs baseline: 7.3028x; 1.3513x over previous
#include <cuda_runtime.h>
#include <cuda_fp16.h>
#include <cstdint>

// ============================================================================
// StyleGAN2 ModulatedConv2D via Winograd F(2x2,3x3) + HMMA mma.sync GEMMs.
//   U[xi][co][ci] = G w G^T            (weight transform, fp16, 16 mats)
//   D[xi][tg][ci] = B^T (s*x patch) B  (input transform + modulation, fp16)
//   M[xi][tg][co] = D[xi] @ U[xi]^T    (16 GEMMs, HMMA fp16->fp32, M fp32)
//   out(2x2 tile) = demod*RC_W * A^T M A
// tg = n*1024 + ty*32 + tx  (8 images x 32x32 tiles of 2x2 outputs)
// 2.25x fewer MACs than direct conv; mma.sync issue floor ~238us.
// ============================================================================

#define CIN     512
#define COUT    512
#define LATENTD 512
#define NBATCH  8
#define HW      4096
#define NTILES  8192              // 8 * 32 * 32
#define NCH     16                // K = 512 -> 16 chunks of 32
#define PITCH   80                // 64B payload + 16B pad
#define A_BYTES (128 * PITCH)     // 10240
#define STG_B   (2 * A_BYTES)     // 20480
#define SMEM_SZ (3 * STG_B)       // 61440 dynamic

#define RC_W 0.014731391274719738f   // 1/sqrt(9*512)
#define RC_S 0.04419417382415922f    // 1/sqrt(512)

__device__ float g_style[NBATCH * CIN];
__device__ float g_demod[NBATCH * COUT];
__device__ float g_wsq[CIN * COUT];
__device__ __align__(16) __half g_U[(size_t)16 * COUT * CIN];    // [xi][co][ci]
__device__ __align__(16) __half g_D[(size_t)16 * NTILES * CIN];  // [xi][tg][ci]
__device__ __align__(16) float  g_M[(size_t)16 * NTILES * COUT]; // [xi][tg][co]

// ---------------- PTX helpers ----------------------------------------------
__device__ __forceinline__ uint32_t smem_u32(const void* p) {
    uint32_t a;
    asm("{ .reg .u64 t; cvta.to.shared.u64 t, %1; cvt.u32.u64 %0, t; }"
        : "=r"(a) : "l"(p));
    return a;
}
__device__ __forceinline__ void cp16(uint32_t s, const void* g) {
    asm volatile("cp.async.cg.shared.global [%0], [%1], 16;"
                 :: "r"(s), "l"(g) : "memory");
}
#define CP_COMMIT() asm volatile("cp.async.commit_group;" ::: "memory")
#define CP_WAIT1()  asm volatile("cp.async.wait_group 1;" ::: "memory")
#define CP_WAIT0()  asm volatile("cp.async.wait_group 0;" ::: "memory")

#define LDSM4(r, addr) \
    asm volatile("ldmatrix.sync.aligned.m8n8.x4.shared.b16 {%0,%1,%2,%3}, [%4];" \
                 : "=r"((r)[0]), "=r"((r)[1]), "=r"((r)[2]), "=r"((r)[3]) \
                 : "r"(addr))

#define MMA16816(d, a, b0, b1) \
    asm volatile("mma.sync.aligned.m16n8k16.row.col.f32.f16.f16.f32 " \
                 "{%0,%1,%2,%3},{%4,%5,%6,%7},{%8,%9},{%0,%1,%2,%3};" \
                 : "+f"((d)[0]), "+f"((d)[1]), "+f"((d)[2]), "+f"((d)[3]) \
                 : "r"((a)[0]), "r"((a)[1]), "r"((a)[2]), "r"((a)[3]), \
                   "r"(b0), "r"(b1))

// ---------------- style / demod (validated since R3) ------------------------
__global__ void style_k(const float* __restrict__ dl,
                        const float* __restrict__ mw,
                        const float* __restrict__ mb) {
    const int n = blockIdx.x, ci = threadIdx.x;
    __shared__ float dls[LATENTD];
    dls[ci] = dl[n * LATENTD + ci];
    __syncthreads();
    float acc = 0.0f;
#pragma unroll 8
    for (int l = 0; l < LATENTD; l++) acc += dls[l] * mw[l * CIN + ci];
    g_style[n * CIN + ci] = acc * RC_S + mb[ci] + 1.0f;
}

__global__ void demod_k() {
    const int n = blockIdx.x, co = threadIdx.x;
    __shared__ float s2[CIN];
    float sv = g_style[n * CIN + co];
    s2[co] = sv * sv;
    __syncthreads();
    float acc = 0.0f;
#pragma unroll 8
    for (int ci = 0; ci < CIN; ci++) acc += s2[ci] * g_wsq[ci * COUT + co];
    g_demod[n * COUT + co] = rsqrtf(acc * (RC_W * RC_W) + 1e-8f);
}

// ---------------- weight transform: U = G w G^T (+ wsq) ---------------------
// w[kk][ci][co] fp32 -> g_U[xi][co][ci] fp16, xi = i*4+j
__global__ void wT_k(const float* __restrict__ w) {
    __shared__ float sw[9][32][33];
    const int tx = threadIdx.x, ty = threadIdx.y;
    const int ci0 = blockIdx.x * 32, co0 = blockIdx.y * 32;
#pragma unroll
    for (int kk = 0; kk < 9; kk++)
#pragma unroll
        for (int r = 0; r < 4; r++)
            sw[kk][ty + r * 8][tx] =
                w[((size_t)kk * CIN + ci0 + ty + r * 8) * COUT + co0 + tx];
    __syncthreads();
#pragma unroll
    for (int q = 0; q < 4; q++) {
        const int col = ty + q * 8;
        const int ci = ci0 + tx, co = co0 + col;
        float g[9], sq = 0.0f;
#pragma unroll
        for (int kk = 0; kk < 9; kk++) {
            g[kk] = sw[kk][tx][col];
            sq += g[kk] * g[kk];
        }
        g_wsq[ci * COUT + co] = sq;
        // rows: t = G * g  (4x3), G = [[1,0,0],[.5,.5,.5],[.5,-.5,.5],[0,0,1]]
        float t[4][3];
#pragma unroll
        for (int c = 0; c < 3; c++) {
            const float a = g[c], b = g[3 + c], d = g[6 + c];
            t[0][c] = a;
            t[1][c] = 0.5f * (a + b + d);
            t[2][c] = 0.5f * (a - b + d);
            t[3][c] = d;
        }
        // cols: U = t * G^T (4x4)
#pragma unroll
        for (int r = 0; r < 4; r++) {
            const float a = t[r][0], b = t[r][1], d = t[r][2];
            float u[4];
            u[0] = a;
            u[1] = 0.5f * (a + b + d);
            u[2] = 0.5f * (a - b + d);
            u[3] = d;
#pragma unroll
            for (int c = 0; c < 4; c++)
                g_U[((size_t)(r * 4 + c) * COUT + co) * CIN + ci] =
                    __float2half(u[c]);
        }
    }
}

// ---------------- input transform: D = B^T (s*d) B ---------------------------
// x[n][ci][64][64] -> g_D[xi][tg][ci] fp16 (half2-packed over ci)
__global__ void xT_k(const float* __restrict__ x) {
    __shared__ float si[4 * 64 * 34];   // [row][px][ci], ci stride 34
    const int tid = threadIdx.x;
    const int ci0 = blockIdx.x * 32, ty = blockIdx.y, n = blockIdx.z;

    for (int idx = tid; idx < 4 * 64 * 32; idx += 256) {
        const int ci_l = idx >> 8, rem = idx & 255;
        const int row = rem >> 6, px = rem & 63;
        const int gy = 2 * ty - 1 + row;
        const float v = ((unsigned)gy < 64u)
            ? x[((size_t)(n * CIN + ci0 + ci_l) * 64 + gy) * 64 + px] : 0.0f;
        si[(row * 64 + px) * 34 + ci_l] = v;
    }
    __syncthreads();

    const int cp = tid & 15;            // ci pair: ci_l = 2*cp, 2*cp+1
    const int tgrp = tid >> 4;          // 0..15 -> tiles tgrp, tgrp+16
    const float sv0 = g_style[n * CIN + ci0 + 2 * cp];
    const float sv1 = g_style[n * CIN + ci0 + 2 * cp + 1];

#pragma unroll
    for (int tt = 0; tt < 2; tt++) {
        const int tx = tgrp + tt * 16;
        const int tg = n * 1024 + ty * 32 + tx;
        float d0[4][4], d1[4][4];
#pragma unroll
        for (int i = 0; i < 4; i++)
#pragma unroll
            for (int j = 0; j < 4; j++) {
                const int px = 2 * tx - 1 + j;
                if ((unsigned)px < 64u) {
                    const float* p = &si[(i * 64 + px) * 34 + 2 * cp];
                    d0[i][j] = p[0] * sv0;
                    d1[i][j] = p[1] * sv1;
                } else { d0[i][j] = 0.0f; d1[i][j] = 0.0f; }
            }
        // e = B^T d (rows), f = e B (cols): pattern {0-2, 1+2, 2-1, 1-3}
        float e0[4][4], e1[4][4];
#pragma unroll
        for (int j = 0; j < 4; j++) {
            e0[0][j] = d0[0][j] - d0[2][j];  e1[0][j] = d1[0][j] - d1[2][j];
            e0[1][j] = d0[1][j] + d0[2][j];  e1[1][j] = d1[1][j] + d1[2][j];
            e0[2][j] = d0[2][j] - d0[1][j];  e1[2][j] = d1[2][j] - d1[1][j];
            e0[3][j] = d0[1][j] - d0[3][j];  e1[3][j] = d1[1][j] - d1[3][j];
        }
#pragma unroll
        for (int i = 0; i < 4; i++) {
            float f0[4], f1[4];
            f0[0] = e0[i][0] - e0[i][2];  f1[0] = e1[i][0] - e1[i][2];
            f0[1] = e0[i][1] + e0[i][2];  f1[1] = e1[i][1] + e1[i][2];
            f0[2] = e0[i][2] - e0[i][1];  f1[2] = e1[i][2] - e1[i][1];
            f0[3] = e0[i][1] - e0[i][3];  f1[3] = e1[i][1] - e1[i][3];
#pragma unroll
            for (int j = 0; j < 4; j++) {
                __half2 hv = __floats2half2_rn(f0[j], f1[j]);
                *(__half2*)&g_D[((size_t)(i * 4 + j) * NTILES + tg) * CIN +
                                ci0 + 2 * cp] = hv;
            }
        }
    }
}

// ---------------- 16 GEMMs: M[xi] = D[xi] @ U[xi]^T (HMMA, R7-proven core) --
__global__ void __launch_bounds__(256, 2) gemm_k() {
    extern __shared__ __align__(128) char dsm[];

    const int tid = threadIdx.x;
    const int wid = tid >> 5, lane = tid & 31;
    const int xi = blockIdx.z;
    const int co0 = blockIdx.y * 128;
    const int m0 = blockIdx.x * 128;
    const int wm = (wid & 1) * 64;
    const int wn = (wid >> 1) * 32;

    const uint32_t sbase = smem_u32(dsm);

    const int arow = tid >> 1, ahalf = tid & 1;
    const uint32_t rc_st = (uint32_t)(arow * PITCH + ahalf * 32);
    const __half* ga_base =
        g_D + ((size_t)xi * NTILES + m0 + arow) * CIN + ahalf * 16;
    const __half* gb_base =
        g_U + ((size_t)xi * COUT + co0 + arow) * CIN + ahalf * 16;

    auto issue = [&](int j, int st) {
        const int k0 = j << 5;
        const __half* ga = ga_base + k0;
        const uint32_t ab = sbase + st * STG_B + rc_st;
        cp16(ab, ga);
        cp16(ab + 16, ga + 8);
        const __half* gb = gb_base + k0;
        const uint32_t bb = ab + A_BYTES;
        cp16(bb, gb);
        cp16(bb + 16, gb + 8);
    };

    uint32_t a_off[4], b_off[2];
#pragma unroll
    for (int mt = 0; mt < 4; mt++)
        a_off[mt] = (uint32_t)((wm + mt * 16 + (lane & 15)) * PITCH +
                               (lane >> 4) * 16);
#pragma unroll
    for (int bt = 0; bt < 2; bt++)
        b_off[bt] = (uint32_t)(
            (wn + bt * 16 + (lane & 7) + ((lane >> 4) & 1) * 8) * PITCH +
            ((lane >> 3) & 1) * 16) + A_BYTES;

    float acc[4][4][4];
#pragma unroll
    for (int mt = 0; mt < 4; mt++)
#pragma unroll
        for (int nt = 0; nt < 4; nt++)
#pragma unroll
            for (int r = 0; r < 4; r++) acc[mt][nt][r] = 0.0f;

    issue(0, 0); CP_COMMIT();
    issue(1, 1); CP_COMMIT();

    int st = 0, stw = 2;
    for (int i = 0; i < NCH; i++) {
        CP_WAIT1();
        __syncthreads();
        const uint32_t stB = sbase + st * STG_B;
#pragma unroll
        for (int ks = 0; ks < 2; ks++) {
            uint32_t af[4][4], bf[2][4];
#pragma unroll
            for (int mt = 0; mt < 4; mt++)
                LDSM4(af[mt], stB + a_off[mt] + ks * 32);
#pragma unroll
            for (int bt = 0; bt < 2; bt++)
                LDSM4(bf[bt], stB + b_off[bt] + ks * 32);
#pragma unroll
            for (int mt = 0; mt < 4; mt++) {
                MMA16816(acc[mt][0], af[mt], bf[0][0], bf[0][1]);
                MMA16816(acc[mt][1], af[mt], bf[0][2], bf[0][3]);
                MMA16816(acc[mt][2], af[mt], bf[1][0], bf[1][1]);
                MMA16816(acc[mt][3], af[mt], bf[1][2], bf[1][3]);
            }
        }
        if (i + 2 < NCH) issue(i + 2, stw);
        CP_COMMIT();
        st = (st == 2) ? 0 : st + 1;
        stw = (stw == 2) ? 0 : stw + 1;
    }
    CP_WAIT0();

    // epilogue: row-major fp32 M[xi][tg][co]
    float* mb = g_M + (size_t)xi * NTILES * COUT;
#pragma unroll
    for (int nt = 0; nt < 4; nt++) {
        const int col = co0 + wn + nt * 8 + (lane & 3) * 2;
#pragma unroll
        for (int mt = 0; mt < 4; mt++) {
            const int row = m0 + wm + mt * 16 + (lane >> 2);
            *(float2*)&mb[(size_t)row * COUT + col] =
                make_float2(acc[mt][nt][0], acc[mt][nt][1]);
            *(float2*)&mb[(size_t)(row + 8) * COUT + col] =
                make_float2(acc[mt][nt][2], acc[mt][nt][3]);
        }
    }
}

// ---------------- output transform: out = demod*RC_W * A^T M A ---------------
__global__ void outT_k(float* __restrict__ out) {
    __shared__ float sm[16 * 32 * 17];  // [xi][t][c], c stride 17
    const int tid = threadIdx.x;
    const int co0 = blockIdx.x * 16, ty = blockIdx.y, n = blockIdx.z;
    const int tg0 = n * 1024 + ty * 32;

    for (int idx = tid; idx < 16 * 32 * 4; idx += 256) {
        const int c4 = idx & 3, t = (idx >> 2) & 31, xi = idx >> 7;
        const float4 v = *(const float4*)&g_M[
            ((size_t)xi * NTILES + tg0 + t) * COUT + co0 + c4 * 4];
        float* s = &sm[(xi * 32 + t) * 17 + c4 * 4];
        s[0] = v.x; s[1] = v.y; s[2] = v.z; s[3] = v.w;
    }
    __syncthreads();

    const int t = tid & 31;             // tile tx
    const int cgrp = tid >> 5;          // 0..7
#pragma unroll
    for (int cc = 0; cc < 2; cc++) {
        const int c = cgrp + cc * 8;
        const int co = co0 + c;
        float m[16];
#pragma unroll
        for (int xi = 0; xi < 16; xi++) m[xi] = sm[(xi * 32 + t) * 17 + c];
        float g0[4], g1[4];
#pragma unroll
        for (int v = 0; v < 4; v++) {
            g0[v] = m[v] + m[4 + v] + m[8 + v];
            g1[v] = m[4 + v] - m[8 + v] - m[12 + v];
        }
        const float dm = g_demod[n * COUT + co] * RC_W;
        const float y00 = (g0[0] + g0[1] + g0[2]) * dm;
        const float y01 = (g0[1] - g0[2] - g0[3]) * dm;
        const float y10 = (g1[0] + g1[1] + g1[2]) * dm;
        const float y11 = (g1[1] - g1[2] - g1[3]) * dm;
        float* ob = out + (((size_t)(n * COUT + co) * 64 + 2 * ty) * 64 + 2 * t);
        *(float2*)ob        = make_float2(y00, y01);
        *(float2*)(ob + 64) = make_float2(y10, y11);
    }
}

// ---------------- launch -----------------------------------------------------
extern "C" void kernel_launch(void* const* d_in, const int* in_sizes, int n_in,
                              void* d_out, int out_size) {
    const float* x  = (const float*)d_in[0];   // [8,512,64,64]
    const float* dl = (const float*)d_in[1];   // [8,512]
    const float* w  = (const float*)d_in[2];   // [3,3,512,512]
    const float* mw = (const float*)d_in[3];   // [512,512]
    const float* mb = (const float*)d_in[4];   // [512]
    float* out = (float*)d_out;                // [8,512,64,64]

    cudaFuncSetAttribute(gemm_k, cudaFuncAttributeMaxDynamicSharedMemorySize,
                         SMEM_SZ);

    style_k<<<NBATCH, 512>>>(dl, mw, mb);
    wT_k<<<dim3(CIN / 32, COUT / 32), dim3(32, 8)>>>(w);
    demod_k<<<NBATCH, 512>>>();
    xT_k<<<dim3(CIN / 32, 32, NBATCH), 256>>>(x);
    gemm_k<<<dim3(NTILES / 128, COUT / 128, 16), 256, SMEM_SZ>>>();
    outT_k<<<dim3(COUT / 16, 32, NBATCH), 256>>>(out);
}

// round 10
// speedup vs baseline: 7.7215x; 1.0573x over previous
#include <cuda_runtime.h>
#include <cuda_fp16.h>
#include <cstdint>

// ============================================================================
// StyleGAN2 ModulatedConv2D via Winograd F(2x2,3x3) + HMMA mma.sync GEMMs.
//   U[xi][co][ci] = G w G^T            (weight transform, fp16, 16 mats)
//   D[xi][tg][ci] = B^T (s*x patch) B  (input transform + modulation, fp16)
//   M[xi][tg][co] = D[xi] @ U[xi]^T    (16 GEMMs, HMMA fp16->fp32)
//   out(2x2 tile) = demod*RC_W * A^T M A
// R10: M stored fp16 (halves inter-stage traffic 256MB -> 128MB).
// ============================================================================

#define CIN     512
#define COUT    512
#define LATENTD 512
#define NBATCH  8
#define HW      4096
#define NTILES  8192              // 8 * 32 * 32
#define NCH     16                // K = 512 -> 16 chunks of 32
#define PITCH   80                // 64B payload + 16B pad
#define A_BYTES (128 * PITCH)     // 10240
#define STG_B   (2 * A_BYTES)     // 20480
#define SMEM_SZ (3 * STG_B)       // 61440 dynamic

#define RC_W 0.014731391274719738f   // 1/sqrt(9*512)
#define RC_S 0.04419417382415922f    // 1/sqrt(512)

__device__ float g_style[NBATCH * CIN];
__device__ float g_demod[NBATCH * COUT];
__device__ float g_wsq[CIN * COUT];
__device__ __align__(16) __half g_U[(size_t)16 * COUT * CIN];    // [xi][co][ci]
__device__ __align__(16) __half g_D[(size_t)16 * NTILES * CIN];  // [xi][tg][ci]
__device__ __align__(16) __half g_M[(size_t)16 * NTILES * COUT]; // [xi][tg][co]

// ---------------- PTX helpers ----------------------------------------------
__device__ __forceinline__ uint32_t smem_u32(const void* p) {
    uint32_t a;
    asm("{ .reg .u64 t; cvta.to.shared.u64 t, %1; cvt.u32.u64 %0, t; }"
        : "=r"(a) : "l"(p));
    return a;
}
__device__ __forceinline__ void cp16(uint32_t s, const void* g) {
    asm volatile("cp.async.cg.shared.global [%0], [%1], 16;"
                 :: "r"(s), "l"(g) : "memory");
}
#define CP_COMMIT() asm volatile("cp.async.commit_group;" ::: "memory")
#define CP_WAIT1()  asm volatile("cp.async.wait_group 1;" ::: "memory")
#define CP_WAIT0()  asm volatile("cp.async.wait_group 0;" ::: "memory")

#define LDSM4(r, addr) \
    asm volatile("ldmatrix.sync.aligned.m8n8.x4.shared.b16 {%0,%1,%2,%3}, [%4];" \
                 : "=r"((r)[0]), "=r"((r)[1]), "=r"((r)[2]), "=r"((r)[3]) \
                 : "r"(addr))

#define MMA16816(d, a, b0, b1) \
    asm volatile("mma.sync.aligned.m16n8k16.row.col.f32.f16.f16.f32 " \
                 "{%0,%1,%2,%3},{%4,%5,%6,%7},{%8,%9},{%0,%1,%2,%3};" \
                 : "+f"((d)[0]), "+f"((d)[1]), "+f"((d)[2]), "+f"((d)[3]) \
                 : "r"((a)[0]), "r"((a)[1]), "r"((a)[2]), "r"((a)[3]), \
                   "r"(b0), "r"(b1))

// ---------------- style / demod (validated since R3) ------------------------
__global__ void style_k(const float* __restrict__ dl,
                        const float* __restrict__ mw,
                        const float* __restrict__ mb) {
    const int n = blockIdx.x, ci = threadIdx.x;
    __shared__ float dls[LATENTD];
    dls[ci] = dl[n * LATENTD + ci];
    __syncthreads();
    float acc = 0.0f;
#pragma unroll 8
    for (int l = 0; l < LATENTD; l++) acc += dls[l] * mw[l * CIN + ci];
    g_style[n * CIN + ci] = acc * RC_S + mb[ci] + 1.0f;
}

__global__ void demod_k() {
    const int n = blockIdx.x, co = threadIdx.x;
    __shared__ float s2[CIN];
    float sv = g_style[n * CIN + co];
    s2[co] = sv * sv;
    __syncthreads();
    float acc = 0.0f;
#pragma unroll 8
    for (int ci = 0; ci < CIN; ci++) acc += s2[ci] * g_wsq[ci * COUT + co];
    g_demod[n * COUT + co] = rsqrtf(acc * (RC_W * RC_W) + 1e-8f);
}

// ---------------- weight transform: U = G w G^T (+ wsq) ---------------------
__global__ void wT_k(const float* __restrict__ w) {
    __shared__ float sw[9][32][33];
    const int tx = threadIdx.x, ty = threadIdx.y;
    const int ci0 = blockIdx.x * 32, co0 = blockIdx.y * 32;
#pragma unroll
    for (int kk = 0; kk < 9; kk++)
#pragma unroll
        for (int r = 0; r < 4; r++)
            sw[kk][ty + r * 8][tx] =
                w[((size_t)kk * CIN + ci0 + ty + r * 8) * COUT + co0 + tx];
    __syncthreads();
#pragma unroll
    for (int q = 0; q < 4; q++) {
        const int col = ty + q * 8;
        const int ci = ci0 + tx, co = co0 + col;
        float g[9], sq = 0.0f;
#pragma unroll
        for (int kk = 0; kk < 9; kk++) {
            g[kk] = sw[kk][tx][col];
            sq += g[kk] * g[kk];
        }
        g_wsq[ci * COUT + co] = sq;
        float t[4][3];
#pragma unroll
        for (int c = 0; c < 3; c++) {
            const float a = g[c], b = g[3 + c], d = g[6 + c];
            t[0][c] = a;
            t[1][c] = 0.5f * (a + b + d);
            t[2][c] = 0.5f * (a - b + d);
            t[3][c] = d;
        }
#pragma unroll
        for (int r = 0; r < 4; r++) {
            const float a = t[r][0], b = t[r][1], d = t[r][2];
            float u[4];
            u[0] = a;
            u[1] = 0.5f * (a + b + d);
            u[2] = 0.5f * (a - b + d);
            u[3] = d;
#pragma unroll
            for (int c = 0; c < 4; c++)
                g_U[((size_t)(r * 4 + c) * COUT + co) * CIN + ci] =
                    __float2half(u[c]);
        }
    }
}

// ---------------- input transform: D = B^T (s*d) B ---------------------------
__global__ void xT_k(const float* __restrict__ x) {
    __shared__ float si[4 * 64 * 34];   // [row][px][ci], ci stride 34
    const int tid = threadIdx.x;
    const int ci0 = blockIdx.x * 32, ty = blockIdx.y, n = blockIdx.z;

    for (int idx = tid; idx < 4 * 64 * 32; idx += 256) {
        const int ci_l = idx >> 8, rem = idx & 255;
        const int row = rem >> 6, px = rem & 63;
        const int gy = 2 * ty - 1 + row;
        const float v = ((unsigned)gy < 64u)
            ? x[((size_t)(n * CIN + ci0 + ci_l) * 64 + gy) * 64 + px] : 0.0f;
        si[(row * 64 + px) * 34 + ci_l] = v;
    }
    __syncthreads();

    const int cp = tid & 15;
    const int tgrp = tid >> 4;
    const float sv0 = g_style[n * CIN + ci0 + 2 * cp];
    const float sv1 = g_style[n * CIN + ci0 + 2 * cp + 1];

#pragma unroll
    for (int tt = 0; tt < 2; tt++) {
        const int tx = tgrp + tt * 16;
        const int tg = n * 1024 + ty * 32 + tx;
        float d0[4][4], d1[4][4];
#pragma unroll
        for (int i = 0; i < 4; i++)
#pragma unroll
            for (int j = 0; j < 4; j++) {
                const int px = 2 * tx - 1 + j;
                if ((unsigned)px < 64u) {
                    const float* p = &si[(i * 64 + px) * 34 + 2 * cp];
                    d0[i][j] = p[0] * sv0;
                    d1[i][j] = p[1] * sv1;
                } else { d0[i][j] = 0.0f; d1[i][j] = 0.0f; }
            }
        float e0[4][4], e1[4][4];
#pragma unroll
        for (int j = 0; j < 4; j++) {
            e0[0][j] = d0[0][j] - d0[2][j];  e1[0][j] = d1[0][j] - d1[2][j];
            e0[1][j] = d0[1][j] + d0[2][j];  e1[1][j] = d1[1][j] + d1[2][j];
            e0[2][j] = d0[2][j] - d0[1][j];  e1[2][j] = d1[2][j] - d1[1][j];
            e0[3][j] = d0[1][j] - d0[3][j];  e1[3][j] = d1[1][j] - d1[3][j];
        }
#pragma unroll
        for (int i = 0; i < 4; i++) {
            float f0[4], f1[4];
            f0[0] = e0[i][0] - e0[i][2];  f1[0] = e1[i][0] - e1[i][2];
            f0[1] = e0[i][1] + e0[i][2];  f1[1] = e1[i][1] + e1[i][2];
            f0[2] = e0[i][2] - e0[i][1];  f1[2] = e1[i][2] - e1[i][1];
            f0[3] = e0[i][1] - e0[i][3];  f1[3] = e1[i][1] - e1[i][3];
#pragma unroll
            for (int j = 0; j < 4; j++) {
                __half2 hv = __floats2half2_rn(f0[j], f1[j]);
                *(__half2*)&g_D[((size_t)(i * 4 + j) * NTILES + tg) * CIN +
                                ci0 + 2 * cp] = hv;
            }
        }
    }
}

// ---------------- 16 GEMMs: M[xi] = D[xi] @ U[xi]^T (HMMA core) --------------
__global__ void __launch_bounds__(256, 2) gemm_k() {
    extern __shared__ __align__(128) char dsm[];

    const int tid = threadIdx.x;
    const int wid = tid >> 5, lane = tid & 31;
    const int xi = blockIdx.z;
    const int co0 = blockIdx.y * 128;
    const int m0 = blockIdx.x * 128;
    const int wm = (wid & 1) * 64;
    const int wn = (wid >> 1) * 32;

    const uint32_t sbase = smem_u32(dsm);

    const int arow = tid >> 1, ahalf = tid & 1;
    const uint32_t rc_st = (uint32_t)(arow * PITCH + ahalf * 32);
    const __half* ga_base =
        g_D + ((size_t)xi * NTILES + m0 + arow) * CIN + ahalf * 16;
    const __half* gb_base =
        g_U + ((size_t)xi * COUT + co0 + arow) * CIN + ahalf * 16;

    auto issue = [&](int j, int st) {
        const int k0 = j << 5;
        const __half* ga = ga_base + k0;
        const uint32_t ab = sbase + st * STG_B + rc_st;
        cp16(ab, ga);
        cp16(ab + 16, ga + 8);
        const __half* gb = gb_base + k0;
        const uint32_t bb = ab + A_BYTES;
        cp16(bb, gb);
        cp16(bb + 16, gb + 8);
    };

    uint32_t a_off[4], b_off[2];
#pragma unroll
    for (int mt = 0; mt < 4; mt++)
        a_off[mt] = (uint32_t)((wm + mt * 16 + (lane & 15)) * PITCH +
                               (lane >> 4) * 16);
#pragma unroll
    for (int bt = 0; bt < 2; bt++)
        b_off[bt] = (uint32_t)(
            (wn + bt * 16 + (lane & 7) + ((lane >> 4) & 1) * 8) * PITCH +
            ((lane >> 3) & 1) * 16) + A_BYTES;

    float acc[4][4][4];
#pragma unroll
    for (int mt = 0; mt < 4; mt++)
#pragma unroll
        for (int nt = 0; nt < 4; nt++)
#pragma unroll
            for (int r = 0; r < 4; r++) acc[mt][nt][r] = 0.0f;

    issue(0, 0); CP_COMMIT();
    issue(1, 1); CP_COMMIT();

    int st = 0, stw = 2;
    for (int i = 0; i < NCH; i++) {
        CP_WAIT1();
        __syncthreads();
        const uint32_t stB = sbase + st * STG_B;
#pragma unroll
        for (int ks = 0; ks < 2; ks++) {
            uint32_t af[4][4], bf[2][4];
#pragma unroll
            for (int mt = 0; mt < 4; mt++)
                LDSM4(af[mt], stB + a_off[mt] + ks * 32);
#pragma unroll
            for (int bt = 0; bt < 2; bt++)
                LDSM4(bf[bt], stB + b_off[bt] + ks * 32);
#pragma unroll
            for (int mt = 0; mt < 4; mt++) {
                MMA16816(acc[mt][0], af[mt], bf[0][0], bf[0][1]);
                MMA16816(acc[mt][1], af[mt], bf[0][2], bf[0][3]);
                MMA16816(acc[mt][2], af[mt], bf[1][0], bf[1][1]);
                MMA16816(acc[mt][3], af[mt], bf[1][2], bf[1][3]);
            }
        }
        if (i + 2 < NCH) issue(i + 2, stw);
        CP_COMMIT();
        st = (st == 2) ? 0 : st + 1;
        stw = (stw == 2) ? 0 : stw + 1;
    }
    CP_WAIT0();

    // epilogue: row-major fp16 M[xi][tg][co]
    __half* mb = g_M + (size_t)xi * NTILES * COUT;
#pragma unroll
    for (int nt = 0; nt < 4; nt++) {
        const int col = co0 + wn + nt * 8 + (lane & 3) * 2;
#pragma unroll
        for (int mt = 0; mt < 4; mt++) {
            const int row = m0 + wm + mt * 16 + (lane >> 2);
            *(__half2*)&mb[(size_t)row * COUT + col] =
                __floats2half2_rn(acc[mt][nt][0], acc[mt][nt][1]);
            *(__half2*)&mb[(size_t)(row + 8) * COUT + col] =
                __floats2half2_rn(acc[mt][nt][2], acc[mt][nt][3]);
        }
    }
}

// ---------------- output transform: out = demod*RC_W * A^T M A ---------------
__global__ void outT_k(float* __restrict__ out) {
    __shared__ float sm[16 * 32 * 17];  // [xi][t][c], c stride 17
    const int tid = threadIdx.x;
    const int co0 = blockIdx.x * 16, ty = blockIdx.y, n = blockIdx.z;
    const int tg0 = n * 1024 + ty * 32;

    for (int idx = tid; idx < 16 * 32 * 2; idx += 256) {
        const int c8 = idx & 1, t = (idx >> 1) & 31, xi = idx >> 6;
        const uint4 v = *(const uint4*)&g_M[
            ((size_t)xi * NTILES + tg0 + t) * COUT + co0 + c8 * 8];
        float* s = &sm[(xi * 32 + t) * 17 + c8 * 8];
        float2 p;
        p = __half22float2(*(__half2*)&v.x); s[0] = p.x; s[1] = p.y;
        p = __half22float2(*(__half2*)&v.y); s[2] = p.x; s[3] = p.y;
        p = __half22float2(*(__half2*)&v.z); s[4] = p.x; s[5] = p.y;
        p = __half22float2(*(__half2*)&v.w); s[6] = p.x; s[7] = p.y;
    }
    __syncthreads();

    const int t = tid & 31;
    const int cgrp = tid >> 5;
#pragma unroll
    for (int cc = 0; cc < 2; cc++) {
        const int c = cgrp + cc * 8;
        const int co = co0 + c;
        float m[16];
#pragma unroll
        for (int xi = 0; xi < 16; xi++) m[xi] = sm[(xi * 32 + t) * 17 + c];
        float g0[4], g1[4];
#pragma unroll
        for (int v = 0; v < 4; v++) {
            g0[v] = m[v] + m[4 + v] + m[8 + v];
            g1[v] = m[4 + v] - m[8 + v] - m[12 + v];
        }
        const float dm = g_demod[n * COUT + co] * RC_W;
        const float y00 = (g0[0] + g0[1] + g0[2]) * dm;
        const float y01 = (g0[1] - g0[2] - g0[3]) * dm;
        const float y10 = (g1[0] + g1[1] + g1[2]) * dm;
        const float y11 = (g1[1] - g1[2] - g1[3]) * dm;
        float* ob = out + (((size_t)(n * COUT + co) * 64 + 2 * ty) * 64 + 2 * t);
        *(float2*)ob        = make_float2(y00, y01);
        *(float2*)(ob + 64) = make_float2(y10, y11);
    }
}

// ---------------- launch -----------------------------------------------------
extern "C" void kernel_launch(void* const* d_in, const int* in_sizes, int n_in,
                              void* d_out, int out_size) {
    const float* x  = (const float*)d_in[0];   // [8,512,64,64]
    const float* dl = (const float*)d_in[1];   // [8,512]
    const float* w  = (const float*)d_in[2];   // [3,3,512,512]
    const float* mw = (const float*)d_in[3];   // [512,512]
    const float* mb = (const float*)d_in[4];   // [512]
    float* out = (float*)d_out;                // [8,512,64,64]

    cudaFuncSetAttribute(gemm_k, cudaFuncAttributeMaxDynamicSharedMemorySize,
                         SMEM_SZ);

    style_k<<<NBATCH, 512>>>(dl, mw, mb);
    wT_k<<<dim3(CIN / 32, COUT / 32), dim3(32, 8)>>>(w);
    demod_k<<<NBATCH, 512>>>();
    xT_k<<<dim3(CIN / 32, 32, NBATCH), 256>>>(x);
    gemm_k<<<dim3(NTILES / 128, COUT / 128, 16), 256, SMEM_SZ>>>();
    outT_k<<<dim3(COUT / 16, 32, NBATCH), 256>>>(out);
}

// round 11
// speedup vs baseline: 7.9101x; 1.0244x over previous
#include <cuda_runtime.h>
#include <cuda_fp16.h>
#include <cstdint>

// ============================================================================
// StyleGAN2 ModulatedConv2D via Winograd F(2x2,3x3) + HMMA mma.sync GEMMs.
//   U[xi][co][ci] = G w G^T            (weight transform, fp16, 16 mats)
//   D[xi][tg][ci] = B^T (s*x patch) B  (input transform + modulation, fp16)
//   M[xi][tg][co] = D[xi] @ U[xi]^T    (16 GEMMs, HMMA fp16->fp32, M fp16)
//   out(2x2 tile) = demod*RC_W * A^T M A
// R11: gemm grid xi-major waves (D slice L2-resident, 4x less DRAM);
//      xT processes 4 tile-rows/CTA (1.25x halo vs 2x, fewer addr ops).
// ============================================================================

#define CIN     512
#define COUT    512
#define LATENTD 512
#define NBATCH  8
#define HW      4096
#define NTILES  8192              // 8 * 32 * 32
#define NCH     16                // K = 512 -> 16 chunks of 32
#define PITCH   80                // 64B payload + 16B pad
#define A_BYTES (128 * PITCH)     // 10240
#define STG_B   (2 * A_BYTES)     // 20480
#define SMEM_SZ (3 * STG_B)       // 61440 dynamic (gemm)

#define XT_PITCH 35               // odd float pitch: conflict-free ld+st
#define XT_SMEM  (10 * 64 * XT_PITCH * 4)   // 89600 dynamic (xT)

#define RC_W 0.014731391274719738f   // 1/sqrt(9*512)
#define RC_S 0.04419417382415922f    // 1/sqrt(512)

__device__ float g_style[NBATCH * CIN];
__device__ float g_demod[NBATCH * COUT];
__device__ float g_wsq[CIN * COUT];
__device__ __align__(16) __half g_U[(size_t)16 * COUT * CIN];    // [xi][co][ci]
__device__ __align__(16) __half g_D[(size_t)16 * NTILES * CIN];  // [xi][tg][ci]
__device__ __align__(16) __half g_M[(size_t)16 * NTILES * COUT]; // [xi][tg][co]

// ---------------- PTX helpers ----------------------------------------------
__device__ __forceinline__ uint32_t smem_u32(const void* p) {
    uint32_t a;
    asm("{ .reg .u64 t; cvta.to.shared.u64 t, %1; cvt.u32.u64 %0, t; }"
        : "=r"(a) : "l"(p));
    return a;
}
__device__ __forceinline__ void cp16(uint32_t s, const void* g) {
    asm volatile("cp.async.cg.shared.global [%0], [%1], 16;"
                 :: "r"(s), "l"(g) : "memory");
}
#define CP_COMMIT() asm volatile("cp.async.commit_group;" ::: "memory")
#define CP_WAIT1()  asm volatile("cp.async.wait_group 1;" ::: "memory")
#define CP_WAIT0()  asm volatile("cp.async.wait_group 0;" ::: "memory")

#define LDSM4(r, addr) \
    asm volatile("ldmatrix.sync.aligned.m8n8.x4.shared.b16 {%0,%1,%2,%3}, [%4];" \
                 : "=r"((r)[0]), "=r"((r)[1]), "=r"((r)[2]), "=r"((r)[3]) \
                 : "r"(addr))

#define MMA16816(d, a, b0, b1) \
    asm volatile("mma.sync.aligned.m16n8k16.row.col.f32.f16.f16.f32 " \
                 "{%0,%1,%2,%3},{%4,%5,%6,%7},{%8,%9},{%0,%1,%2,%3};" \
                 : "+f"((d)[0]), "+f"((d)[1]), "+f"((d)[2]), "+f"((d)[3]) \
                 : "r"((a)[0]), "r"((a)[1]), "r"((a)[2]), "r"((a)[3]), \
                   "r"(b0), "r"(b1))

// ---------------- style / demod (validated since R3) ------------------------
__global__ void style_k(const float* __restrict__ dl,
                        const float* __restrict__ mw,
                        const float* __restrict__ mb) {
    const int n = blockIdx.x, ci = threadIdx.x;
    __shared__ float dls[LATENTD];
    dls[ci] = dl[n * LATENTD + ci];
    __syncthreads();
    float acc = 0.0f;
#pragma unroll 8
    for (int l = 0; l < LATENTD; l++) acc += dls[l] * mw[l * CIN + ci];
    g_style[n * CIN + ci] = acc * RC_S + mb[ci] + 1.0f;
}

__global__ void demod_k() {
    const int n = blockIdx.x, co = threadIdx.x;
    __shared__ float s2[CIN];
    float sv = g_style[n * CIN + co];
    s2[co] = sv * sv;
    __syncthreads();
    float acc = 0.0f;
#pragma unroll 8
    for (int ci = 0; ci < CIN; ci++) acc += s2[ci] * g_wsq[ci * COUT + co];
    g_demod[n * COUT + co] = rsqrtf(acc * (RC_W * RC_W) + 1e-8f);
}

// ---------------- weight transform: U = G w G^T (+ wsq) ---------------------
__global__ void wT_k(const float* __restrict__ w) {
    __shared__ float sw[9][32][33];
    const int tx = threadIdx.x, ty = threadIdx.y;
    const int ci0 = blockIdx.x * 32, co0 = blockIdx.y * 32;
#pragma unroll
    for (int kk = 0; kk < 9; kk++)
#pragma unroll
        for (int r = 0; r < 4; r++)
            sw[kk][ty + r * 8][tx] =
                w[((size_t)kk * CIN + ci0 + ty + r * 8) * COUT + co0 + tx];
    __syncthreads();
#pragma unroll
    for (int q = 0; q < 4; q++) {
        const int col = ty + q * 8;
        const int ci = ci0 + tx, co = co0 + col;
        float g[9], sq = 0.0f;
#pragma unroll
        for (int kk = 0; kk < 9; kk++) {
            g[kk] = sw[kk][tx][col];
            sq += g[kk] * g[kk];
        }
        g_wsq[ci * COUT + co] = sq;
        float t[4][3];
#pragma unroll
        for (int c = 0; c < 3; c++) {
            const float a = g[c], b = g[3 + c], d = g[6 + c];
            t[0][c] = a;
            t[1][c] = 0.5f * (a + b + d);
            t[2][c] = 0.5f * (a - b + d);
            t[3][c] = d;
        }
#pragma unroll
        for (int r = 0; r < 4; r++) {
            const float a = t[r][0], b = t[r][1], d = t[r][2];
            float u[4];
            u[0] = a;
            u[1] = 0.5f * (a + b + d);
            u[2] = 0.5f * (a - b + d);
            u[3] = d;
#pragma unroll
            for (int c = 0; c < 4; c++)
                g_U[((size_t)(r * 4 + c) * COUT + co) * CIN + ci] =
                    __float2half(u[c]);
        }
    }
}

// ---------------- input transform: D = B^T (s*d) B ---------------------------
// R11: 4 tile-rows per CTA. grid (CIN/32, 8, NBATCH), 256 thr, dyn smem 87.5KB.
__global__ void xT_k(const float* __restrict__ x) {
    extern __shared__ __align__(16) float si[];   // [10 rows][64 px][pitch 35]
    const int tid = threadIdx.x;
    const int ci0 = blockIdx.x * 32, by = blockIdx.y, n = blockIdx.z;

    // load 10 input rows x 64 px x 32 ci (zero-fill vertical halo)
    const int px = tid & 63, sub = tid >> 6;      // 4 (row,ci) pairs per pass
#pragma unroll
    for (int it = 0; it < 80; it++) {
        const int pair = it * 4 + sub;            // 0..319
        const int row = pair >> 5, ci_l = pair & 31;
        const int gy = 8 * by - 1 + row;
        const float v = ((unsigned)gy < 64u)
            ? x[((size_t)(n * CIN + ci0 + ci_l) * 64 + gy) * 64 + px] : 0.0f;
        si[(row * 64 + px) * XT_PITCH + ci_l] = v;
    }
    __syncthreads();

    const int cp = tid & 15;                      // ci pair 2cp, 2cp+1
    const int tgrp = tid >> 4;                    // 0..15 -> tx = tgrp, tgrp+16
    const float sv0 = g_style[n * CIN + ci0 + 2 * cp];
    const float sv1 = g_style[n * CIN + ci0 + 2 * cp + 1];

#pragma unroll
    for (int ty_l = 0; ty_l < 4; ty_l++) {
#pragma unroll
        for (int tt = 0; tt < 2; tt++) {
            const int tx = tgrp + tt * 16;
            const int tg = n * 1024 + (4 * by + ty_l) * 32 + tx;
            float d0[4][4], d1[4][4];
#pragma unroll
            for (int i = 0; i < 4; i++)
#pragma unroll
                for (int j = 0; j < 4; j++) {
                    const int pxx = 2 * tx - 1 + j;
                    if ((unsigned)pxx < 64u) {
                        const float* p =
                            &si[((2 * ty_l + i) * 64 + pxx) * XT_PITCH + 2 * cp];
                        d0[i][j] = p[0] * sv0;
                        d1[i][j] = p[1] * sv1;
                    } else { d0[i][j] = 0.0f; d1[i][j] = 0.0f; }
                }
            float e0[4][4], e1[4][4];
#pragma unroll
            for (int j = 0; j < 4; j++) {
                e0[0][j] = d0[0][j] - d0[2][j];  e1[0][j] = d1[0][j] - d1[2][j];
                e0[1][j] = d0[1][j] + d0[2][j];  e1[1][j] = d1[1][j] + d1[2][j];
                e0[2][j] = d0[2][j] - d0[1][j];  e1[2][j] = d1[2][j] - d1[1][j];
                e0[3][j] = d0[1][j] - d0[3][j];  e1[3][j] = d1[1][j] - d1[3][j];
            }
            __half* dst = &g_D[(size_t)tg * CIN + ci0 + 2 * cp];
#pragma unroll
            for (int i = 0; i < 4; i++) {
                float f0[4], f1[4];
                f0[0] = e0[i][0] - e0[i][2];  f1[0] = e1[i][0] - e1[i][2];
                f0[1] = e0[i][1] + e0[i][2];  f1[1] = e1[i][1] + e1[i][2];
                f0[2] = e0[i][2] - e0[i][1];  f1[2] = e1[i][2] - e1[i][1];
                f0[3] = e0[i][1] - e0[i][3];  f1[3] = e1[i][1] - e1[i][3];
#pragma unroll
                for (int j = 0; j < 4; j++)
                    *(__half2*)(dst + (size_t)(i * 4 + j) * NTILES * CIN) =
                        __floats2half2_rn(f0[j], f1[j]);
            }
        }
    }
}

// ---------------- 16 GEMMs: M[xi] = D[xi] @ U[xi]^T (HMMA core) --------------
// R11 grid: (co-block fastest, m-block, xi) -> one wave ~= one xi slice,
// D[xi] (8MB) + U[xi] (0.5MB) L2-resident, D DRAM traffic 512MB -> 128MB.
__global__ void __launch_bounds__(256, 2) gemm_k() {
    extern __shared__ __align__(128) char dsm[];

    const int tid = threadIdx.x;
    const int wid = tid >> 5, lane = tid & 31;
    const int xi = blockIdx.z;
    const int co0 = blockIdx.x * 128;
    const int m0 = blockIdx.y * 128;
    const int wm = (wid & 1) * 64;
    const int wn = (wid >> 1) * 32;

    const uint32_t sbase = smem_u32(dsm);

    const int arow = tid >> 1, ahalf = tid & 1;
    const uint32_t rc_st = (uint32_t)(arow * PITCH + ahalf * 32);
    const __half* ga_base =
        g_D + ((size_t)xi * NTILES + m0 + arow) * CIN + ahalf * 16;
    const __half* gb_base =
        g_U + ((size_t)xi * COUT + co0 + arow) * CIN + ahalf * 16;

    auto issue = [&](int j, int st) {
        const int k0 = j << 5;
        const __half* ga = ga_base + k0;
        const uint32_t ab = sbase + st * STG_B + rc_st;
        cp16(ab, ga);
        cp16(ab + 16, ga + 8);
        const __half* gb = gb_base + k0;
        const uint32_t bb = ab + A_BYTES;
        cp16(bb, gb);
        cp16(bb + 16, gb + 8);
    };

    uint32_t a_off[4], b_off[2];
#pragma unroll
    for (int mt = 0; mt < 4; mt++)
        a_off[mt] = (uint32_t)((wm + mt * 16 + (lane & 15)) * PITCH +
                               (lane >> 4) * 16);
#pragma unroll
    for (int bt = 0; bt < 2; bt++)
        b_off[bt] = (uint32_t)(
            (wn + bt * 16 + (lane & 7) + ((lane >> 4) & 1) * 8) * PITCH +
            ((lane >> 3) & 1) * 16) + A_BYTES;

    float acc[4][4][4];
#pragma unroll
    for (int mt = 0; mt < 4; mt++)
#pragma unroll
        for (int nt = 0; nt < 4; nt++)
#pragma unroll
            for (int r = 0; r < 4; r++) acc[mt][nt][r] = 0.0f;

    issue(0, 0); CP_COMMIT();
    issue(1, 1); CP_COMMIT();

    int st = 0, stw = 2;
    for (int i = 0; i < NCH; i++) {
        CP_WAIT1();
        __syncthreads();
        const uint32_t stB = sbase + st * STG_B;
#pragma unroll
        for (int ks = 0; ks < 2; ks++) {
            uint32_t af[4][4], bf[2][4];
#pragma unroll
            for (int mt = 0; mt < 4; mt++)
                LDSM4(af[mt], stB + a_off[mt] + ks * 32);
#pragma unroll
            for (int bt = 0; bt < 2; bt++)
                LDSM4(bf[bt], stB + b_off[bt] + ks * 32);
#pragma unroll
            for (int mt = 0; mt < 4; mt++) {
                MMA16816(acc[mt][0], af[mt], bf[0][0], bf[0][1]);
                MMA16816(acc[mt][1], af[mt], bf[0][2], bf[0][3]);
                MMA16816(acc[mt][2], af[mt], bf[1][0], bf[1][1]);
                MMA16816(acc[mt][3], af[mt], bf[1][2], bf[1][3]);
            }
        }
        if (i + 2 < NCH) issue(i + 2, stw);
        CP_COMMIT();
        st = (st == 2) ? 0 : st + 1;
        stw = (stw == 2) ? 0 : stw + 1;
    }
    CP_WAIT0();

    // epilogue: row-major fp16 M[xi][tg][co]
    __half* mbp = g_M + (size_t)xi * NTILES * COUT;
#pragma unroll
    for (int nt = 0; nt < 4; nt++) {
        const int col = co0 + wn + nt * 8 + (lane & 3) * 2;
#pragma unroll
        for (int mt = 0; mt < 4; mt++) {
            const int row = m0 + wm + mt * 16 + (lane >> 2);
            *(__half2*)&mbp[(size_t)row * COUT + col] =
                __floats2half2_rn(acc[mt][nt][0], acc[mt][nt][1]);
            *(__half2*)&mbp[(size_t)(row + 8) * COUT + col] =
                __floats2half2_rn(acc[mt][nt][2], acc[mt][nt][3]);
        }
    }
}

// ---------------- output transform: out = demod*RC_W * A^T M A ---------------
__global__ void outT_k(float* __restrict__ out) {
    __shared__ float sm[16 * 32 * 17];  // [xi][t][c], c stride 17
    const int tid = threadIdx.x;
    const int co0 = blockIdx.x * 16, ty = blockIdx.y, n = blockIdx.z;
    const int tg0 = n * 1024 + ty * 32;

    for (int idx = tid; idx < 16 * 32 * 2; idx += 256) {
        const int c8 = idx & 1, t = (idx >> 1) & 31, xi = idx >> 6;
        const uint4 v = *(const uint4*)&g_M[
            ((size_t)xi * NTILES + tg0 + t) * COUT + co0 + c8 * 8];
        float* s = &sm[(xi * 32 + t) * 17 + c8 * 8];
        float2 p;
        p = __half22float2(*(__half2*)&v.x); s[0] = p.x; s[1] = p.y;
        p = __half22float2(*(__half2*)&v.y); s[2] = p.x; s[3] = p.y;
        p = __half22float2(*(__half2*)&v.z); s[4] = p.x; s[5] = p.y;
        p = __half22float2(*(__half2*)&v.w); s[6] = p.x; s[7] = p.y;
    }
    __syncthreads();

    const int t = tid & 31;
    const int cgrp = tid >> 5;
#pragma unroll
    for (int cc = 0; cc < 2; cc++) {
        const int c = cgrp + cc * 8;
        const int co = co0 + c;
        float m[16];
#pragma unroll
        for (int xi = 0; xi < 16; xi++) m[xi] = sm[(xi * 32 + t) * 17 + c];
        float g0[4], g1[4];
#pragma unroll
        for (int v = 0; v < 4; v++) {
            g0[v] = m[v] + m[4 + v] + m[8 + v];
            g1[v] = m[4 + v] - m[8 + v] - m[12 + v];
        }
        const float dm = g_demod[n * COUT + co] * RC_W;
        const float y00 = (g0[0] + g0[1] + g0[2]) * dm;
        const float y01 = (g0[1] - g0[2] - g0[3]) * dm;
        const float y10 = (g1[0] + g1[1] + g1[2]) * dm;
        const float y11 = (g1[1] - g1[2] - g1[3]) * dm;
        float* ob = out + (((size_t)(n * COUT + co) * 64 + 2 * ty) * 64 + 2 * t);
        *(float2*)ob        = make_float2(y00, y01);
        *(float2*)(ob + 64) = make_float2(y10, y11);
    }
}

// ---------------- launch -----------------------------------------------------
extern "C" void kernel_launch(void* const* d_in, const int* in_sizes, int n_in,
                              void* d_out, int out_size) {
    const float* x  = (const float*)d_in[0];   // [8,512,64,64]
    const float* dl = (const float*)d_in[1];   // [8,512]
    const float* w  = (const float*)d_in[2];   // [3,3,512,512]
    const float* mw = (const float*)d_in[3];   // [512,512]
    const float* mb = (const float*)d_in[4];   // [512]
    float* out = (float*)d_out;                // [8,512,64,64]

    cudaFuncSetAttribute(gemm_k, cudaFuncAttributeMaxDynamicSharedMemorySize,
                         SMEM_SZ);
    cudaFuncSetAttribute(xT_k, cudaFuncAttributeMaxDynamicSharedMemorySize,
                         XT_SMEM);

    style_k<<<NBATCH, 512>>>(dl, mw, mb);
    wT_k<<<dim3(CIN / 32, COUT / 32), dim3(32, 8)>>>(w);
    demod_k<<<NBATCH, 512>>>();
    xT_k<<<dim3(CIN / 32, 8, NBATCH), 256, XT_SMEM>>>(x);
    gemm_k<<<dim3(COUT / 128, NTILES / 128, 16), 256, SMEM_SZ>>>();
    outT_k<<<dim3(COUT / 16, 32, NBATCH), 256>>>(out);
}